// round 1
// baseline (speedup 1.0000x reference)
#include <cuda_runtime.h>
#include <cstdint>

// Problem constants
#define B_   2
#define C_   64
#define H_   192
#define W_   192
#define HW_  (H_*W_)          // 36864
#define KK_  9
#define HP_  194
#define WP_  194
#define HPWP_ (HP_*WP_)       // 37636
#define CI_  65               // C+1
#define OC_  18               // 2*KK
#define RTOT_ 576             // C*KK

// Scratch (device globals; no allocation allowed)
__device__ float g_xp [B_*C_*HPWP_];   // padded x  (~19.3 MB)
__device__ float g_off[B_*OC_*HW_];    // offsets   (~5.3 MB)
__device__ float g_wt [RTOT_*C_];      // transposed weight [576][64]

// ---------------------------------------------------------------------------
// Kernel 1: zero-pad x into g_xp
// ---------------------------------------------------------------------------
__global__ void pad_kernel(const float* __restrict__ x) {
    int idx = blockIdx.x * blockDim.x + threadIdx.x;
    if (idx >= B_*C_*HPWP_) return;
    int pw = idx % WP_;
    int t  = idx / WP_;
    int ph = t % HP_;
    int bc = t / HP_;
    float v = 0.f;
    if (ph >= 1 && ph <= H_ && pw >= 1 && pw <= W_)
        v = x[(size_t)bc * HW_ + (ph - 1) * W_ + (pw - 1)];
    g_xp[idx] = v;
}

// ---------------------------------------------------------------------------
// Kernel 2: transpose weight [64][576] -> g_wt [576][64]
// ---------------------------------------------------------------------------
__global__ void wt_kernel(const float* __restrict__ w) {
    int idx = blockIdx.x * blockDim.x + threadIdx.x;
    if (idx >= C_*RTOT_) return;
    int o = idx / RTOT_;
    int i = idx % RTOT_;
    g_wt[i * C_ + o] = w[idx];
}

// ---------------------------------------------------------------------------
// Kernel 3: offset-predicting conv.
// input: concat(x, depth) [65 ch], weight_offset [18][65][3][3], pad=1.
// Each thread computes 18 outputs for 2 pixels (p and p+256).
// ---------------------------------------------------------------------------
__global__ __launch_bounds__(256) void offconv_kernel(
    const float* __restrict__ x, const float* __restrict__ depth,
    const float* __restrict__ w_off, const float* __restrict__ bias)
{
    __shared__ float w_s[OC_*CI_*KK_];   // 10530 floats, 42.1 KB
    const int tid = threadIdx.x;
    const int b   = blockIdx.y;

    for (int i = tid; i < OC_*CI_*KK_; i += 256) w_s[i] = w_off[i];
    __syncthreads();

    const int p0 = blockIdx.x * 512 + tid;
    const int p1 = p0 + 256;

    // precompute tap indices (-1 => out of bounds)
    int ti0[KK_], ti1[KK_];
    {
        int oh0 = p0 / W_, ow0 = p0 % W_;
        int oh1 = p1 / W_, ow1 = p1 % W_;
        #pragma unroll
        for (int t = 0; t < KK_; ++t) {
            int ky = t / 3 - 1, kx = t % 3 - 1;
            int ih0 = oh0 + ky, iw0 = ow0 + kx;
            int ih1 = oh1 + ky, iw1 = ow1 + kx;
            ti0[t] = (ih0 >= 0 && ih0 < H_ && iw0 >= 0 && iw0 < W_) ? ih0 * W_ + iw0 : -1;
            ti1[t] = (ih1 >= 0 && ih1 < H_ && iw1 >= 0 && iw1 < W_) ? ih1 * W_ + iw1 : -1;
        }
    }

    float acc0[OC_], acc1[OC_];
    #pragma unroll
    for (int o = 0; o < OC_; ++o) { float bo = bias[o]; acc0[o] = bo; acc1[o] = bo; }

    for (int c = 0; c < CI_; ++c) {
        const float* plane = (c < C_) ? (x + ((size_t)b * C_ + c) * HW_)
                                      : (depth + (size_t)b * HW_);
        float v0[KK_], v1[KK_];
        #pragma unroll
        for (int t = 0; t < KK_; ++t) {
            v0[t] = (ti0[t] >= 0) ? plane[ti0[t]] : 0.f;
            v1[t] = (ti1[t] >= 0) ? plane[ti1[t]] : 0.f;
        }
        #pragma unroll
        for (int o = 0; o < OC_; ++o) {
            const float* wp = &w_s[(o * CI_ + c) * KK_];
            #pragma unroll
            for (int t = 0; t < KK_; ++t) {
                float w = wp[t];
                acc0[o] = fmaf(v0[t], w, acc0[o]);
                acc1[o] = fmaf(v1[t], w, acc1[o]);
            }
        }
    }

    #pragma unroll
    for (int o = 0; o < OC_; ++o) {
        g_off[((size_t)b * OC_ + o) * HW_ + p0] = acc0[o];
        g_off[((size_t)b * OC_ + o) * HW_ + p1] = acc1[o];
    }
}

// ---------------------------------------------------------------------------
// Kernel 4: fused bilinear gather + GEMM.
// Tile: 64 pixels x 64 out channels per block. K=576 split into 8 chunks of
// 72 rows (8 input channels x 9 taps). 256 threads, 4x4 micro-tile each.
// ---------------------------------------------------------------------------
#define TP_  64   // pixels per tile
#define CH_  8    // channels per chunk
#define RC_  (CH_*KK_)   // 72 rows per chunk
#define NC_  (C_/CH_)    // 8 chunks

__global__ __launch_bounds__(256) void fused_kernel(
    const float* __restrict__ unused_x, float* __restrict__ out)
{
    __shared__ __align__(16) float cols_s[RC_*TP_];   // 18432 B
    __shared__ __align__(16) float w_s   [RC_*TP_];   // 18432 B
    __shared__ float4 tap_w  [KK_*TP_];               //  9216 B
    __shared__ int    tap_idx[KK_*TP_];               //  2304 B

    const int tid  = threadIdx.x;
    const int b    = blockIdx.y;
    const int pix0 = blockIdx.x * TP_;

    // ---- phase 0: per-pixel tap coordinates (576 entries) ----
    for (int e = tid; e < KK_*TP_; e += 256) {
        int kk = e / TP_;
        int p  = e % TP_;
        int pix = pix0 + p;
        int oh = pix / W_, ow = pix % W_;
        float ox = g_off[((size_t)b * OC_ + kk) * HW_ + pix];
        float oy = g_off[((size_t)b * OC_ + KK_ + kk) * HW_ + pix];
        float cx = (float)(oh + 1 + (kk / 3) - 1) + ox;
        float cy = (float)(ow + 1 + (kk % 3) - 1) + oy;
        cx = fminf(fmaxf(cx, 0.f), (float)(HP_ - 1));
        cy = fminf(fmaxf(cy, 0.f), (float)(WP_ - 1));
        int tlx = (int)floorf(cx); tlx = min(max(tlx, 0), HP_ - 2);
        int tly = (int)floorf(cy); tly = min(max(tly, 0), WP_ - 2);
        float tlxf = (float)tlx, tlyf = (float)tly;
        float ax = cx - tlxf;          // in [0, 1]
        float ay = cy - tlyf;
        float bx = 1.f - ax;           // (brx - cx)
        float by = 1.f - ay;
        tap_idx[e] = tlx * WP_ + tly;
        tap_w[e]   = make_float4(bx * by, bx * ay, ax * by, ax * ay);
    }

    float acc[4][4];
    #pragma unroll
    for (int i = 0; i < 4; ++i)
        #pragma unroll
        for (int j = 0; j < 4; ++j) acc[i][j] = 0.f;

    const int ow_ = tid >> 4;      // 0..15  -> out channels ow_*4..+3
    const int pw_ = tid & 15;      // 0..15  -> pixels pw_*4..+3

    for (int cc = 0; cc < NC_; ++cc) {
        __syncthreads();   // protect smem reuse (also orders phase-0 on cc==0)

        // fill weight tile (coalesced float4 copy from pre-transposed g_wt)
        {
            const float4* wsrc = reinterpret_cast<const float4*>(g_wt + cc * RC_ * C_);
            float4* wdst = reinterpret_cast<float4*>(w_s);
            #pragma unroll
            for (int e = tid; e < RC_ * TP_ / 4; e += 256) wdst[e] = wsrc[e];
        }

        // fill cols tile: bilinear gather from padded x
        for (int e = tid; e < RC_ * TP_; e += 256) {
            int r  = e >> 6;           // 0..71
            int p  = e & 63;
            int c  = (cc << 3) + r / KK_;
            int kk = r % KK_;
            int t  = kk * TP_ + p;
            int idx = tap_idx[t];
            float4 w = tap_w[t];
            const float* xpc = g_xp + ((size_t)b * C_ + c) * HPWP_;
            float v = w.x * xpc[idx]
                    + w.y * xpc[idx + 1]
                    + w.z * xpc[idx + WP_]
                    + w.w * xpc[idx + WP_ + 1];
            cols_s[e] = v;
        }
        __syncthreads();

        // GEMM micro-kernel: acc[o][p] += w_s[r][o] * cols_s[r][p]
        const float4* w4 = reinterpret_cast<const float4*>(w_s);
        const float4* c4 = reinterpret_cast<const float4*>(cols_s);
        #pragma unroll 8
        for (int r = 0; r < RC_; ++r) {
            float4 wv = w4[r * 16 + ow_];
            float4 cv = c4[r * 16 + pw_];
            acc[0][0] = fmaf(wv.x, cv.x, acc[0][0]);
            acc[0][1] = fmaf(wv.x, cv.y, acc[0][1]);
            acc[0][2] = fmaf(wv.x, cv.z, acc[0][2]);
            acc[0][3] = fmaf(wv.x, cv.w, acc[0][3]);
            acc[1][0] = fmaf(wv.y, cv.x, acc[1][0]);
            acc[1][1] = fmaf(wv.y, cv.y, acc[1][1]);
            acc[1][2] = fmaf(wv.y, cv.z, acc[1][2]);
            acc[1][3] = fmaf(wv.y, cv.w, acc[1][3]);
            acc[2][0] = fmaf(wv.z, cv.x, acc[2][0]);
            acc[2][1] = fmaf(wv.z, cv.y, acc[2][1]);
            acc[2][2] = fmaf(wv.z, cv.z, acc[2][2]);
            acc[2][3] = fmaf(wv.z, cv.w, acc[2][3]);
            acc[3][0] = fmaf(wv.w, cv.x, acc[3][0]);
            acc[3][1] = fmaf(wv.w, cv.y, acc[3][1]);
            acc[3][2] = fmaf(wv.w, cv.z, acc[3][2]);
            acc[3][3] = fmaf(wv.w, cv.w, acc[3][3]);
        }
    }

    // write output: out[b][o][pix], 4 channels x 4 consecutive pixels
    const int o0 = ow_ * 4;
    #pragma unroll
    for (int i = 0; i < 4; ++i) {
        float4 v = make_float4(acc[i][0], acc[i][1], acc[i][2], acc[i][3]);
        *reinterpret_cast<float4*>(
            out + ((size_t)b * C_ + o0 + i) * HW_ + pix0 + pw_ * 4) = v;
    }
}

// ---------------------------------------------------------------------------
// Launch
// ---------------------------------------------------------------------------
extern "C" void kernel_launch(void* const* d_in, const int* in_sizes, int n_in,
                              void* d_out, int out_size) {
    const float* x      = (const float*)d_in[0];  // [2,64,192,192]
    const float* depth  = (const float*)d_in[1];  // [2,1,192,192]
    const float* w_off  = (const float*)d_in[2];  // [18,65,3,3]
    const float* bias   = (const float*)d_in[3];  // [18]
    const float* weight = (const float*)d_in[4];  // [64,64,3,3]
    float* out = (float*)d_out;                   // [2,64,192,192]

    {
        int n = B_*C_*HPWP_;
        pad_kernel<<<(n + 255) / 256, 256>>>(x);
    }
    {
        int n = C_*RTOT_;
        wt_kernel<<<(n + 255) / 256, 256>>>(weight);
    }
    {
        dim3 grid(HW_ / 512, B_);
        offconv_kernel<<<grid, 256>>>(x, depth, w_off, bias);
    }
    {
        dim3 grid(HW_ / TP_, B_);
        fused_kernel<<<grid, 256>>>(x, out);
    }
}